// round 6
// baseline (speedup 1.0000x reference)
#include <cuda_runtime.h>
#include <cooperative_groups.h>
#include <math.h>

namespace cg = cooperative_groups;

// Problem constants
#define T_STEPS 8
#define NB      32          // batch N
#define S_LEN   512         // sequence length S
#define HID     256         // hidden H
#define D_IN    513         // S+1
#define TOTAL   262917      // per-(t,n) output row length
#define P_OFF   260
#define M_OFF   261
#define MN_OFF  262405
#define M_PER_N 262144      // S * ND * H

// Scratch (device globals — no allocation allowed)
__device__ float g_M [NB * M_PER_N];   // [n][s*512 + c]  (c = d*256 + h)
__device__ float g_Mn[NB * 512];       // [n][d*256 + h]
__device__ float g_loc[NB];
__device__ float g_v  [NB];
__device__ int   g_nonzero;

// ---------------- flag kernels ----------------
__global__ void reset_flag_kernel() { g_nonzero = 0; }

__global__ void scan_flag_kernel(const float* __restrict__ rnn) {
    // rnn has NB*TOTAL = 8,413,344 floats = 2,103,336 float4
    const int NV4 = (NB * TOTAL) / 4;
    const float4* p = reinterpret_cast<const float4*>(rnn);
    bool nz = false;
    for (int i = blockIdx.x * blockDim.x + threadIdx.x; i < NV4; i += gridDim.x * blockDim.x) {
        float4 v = p[i];
        nz |= (v.x != 0.f) | (v.y != 0.f) | (v.z != 0.f) | (v.w != 0.f);
    }
    if (__syncthreads_or(nz) && threadIdx.x == 0) atomicOr(&g_nonzero, 1);
}

// ---------------- GRU cluster kernel ----------------
// grid (8, 8, 2): x = column-slice (cluster rank), y = n-group (4 n each), z = direction
// block: 384 threads. Cluster of 8 CTAs along x shares the h state of its 4 batch rows.
struct GruSmem {
    float Ws[96][260];      // weight slice, rows {g*256 + 32*bc + i}, padded stride
    float Hw[4][260];       // full h for the 4 batch rows (padded stride)
    float hbuf[2][4][32];   // own 32-col slice of h_new, double buffered
    float xs[4][512];       // input sequence per batch row
    float wih[96];
    float bih[96];
    float bhh[96];
    float gA[96][4];        // gh part (incl. b_hh)
    float gB[96][4];        // gi part
};

__global__ void __cluster_dims__(8, 1, 1) __launch_bounds__(384, 1)
gru_kernel(const float* __restrict__ inputs,
           const float* __restrict__ w_ih, const float* __restrict__ w_hh,
           const float* __restrict__ b_ih, const float* __restrict__ b_hh)
{
    extern __shared__ float smem_raw[];
    GruSmem* sm = reinterpret_cast<GruSmem*>(smem_raw);

    const int tid = threadIdx.x;
    const int bc  = blockIdx.x;   // column slice (cluster rank)
    const int gN  = blockIdx.y;   // n-group
    const int dd  = blockIdx.z;   // direction

    cg::cluster_group cluster = cg::this_cluster();

    // ---- load weight slice + biases ----
    for (int idx = tid; idx < 96 * 256; idx += 384) {
        int lr = idx >> 8;
        int k  = idx & 255;
        int grow = ((lr >> 5) << 8) + (bc << 5) + (lr & 31);
        sm->Ws[lr][k] = w_hh[(dd * 768 + grow) * 256 + k];
    }
    for (int lr = tid; lr < 96; lr += 384) {
        int grow = ((lr >> 5) << 8) + (bc << 5) + (lr & 31);
        sm->wih[lr] = w_ih[dd * 768 + grow];
        sm->bih[lr] = b_ih[dd * 768 + grow];
        sm->bhh[lr] = b_hh[dd * 768 + grow];
    }
    // input sequence: x0[s,n] = inputs[0][n][s]
    for (int idx = tid; idx < 4 * 512; idx += 384) {
        int nn = idx >> 9, s = idx & 511;
        int n = gN * 4 + nn;
        sm->xs[nn][s] = inputs[n * D_IN + s];
    }
    // h0 = 0
    for (int idx = tid; idx < 4 * 260; idx += 384)
        (&sm->Hw[0][0])[idx] = 0.f;
    __syncthreads();

    const int rr = tid >> 2;   // local gate row 0..95
    const int nn = tid & 3;    // batch row within group
    const float4* wp = reinterpret_cast<const float4*>(&sm->Ws[rr][0]);
    const float4* hp = reinterpret_cast<const float4*>(&sm->Hw[nn][0]);

    for (int t = 0; t < 512; ++t) {
        const int s = dd ? (511 - t) : t;

        // matvec: gh[rr] = sum_k W[rr][k] * h[nn][k]
        float a0 = 0.f, a1 = 0.f, a2 = 0.f, a3 = 0.f;
#pragma unroll 16
        for (int kk = 0; kk < 64; ++kk) {
            float4 w = wp[kk];
            float4 h = hp[kk];
            a0 = fmaf(w.x, h.x, a0);
            a1 = fmaf(w.y, h.y, a1);
            a2 = fmaf(w.z, h.z, a2);
            a3 = fmaf(w.w, h.w, a3);
        }
        float a = (a0 + a1) + (a2 + a3) + sm->bhh[rr];
        float b = fmaf(sm->xs[nn][s], sm->wih[rr], sm->bih[rr]);
        sm->gA[rr][nn] = a;
        sm->gB[rr][nn] = b;
        __syncthreads();

        // gate math: 128 threads = 4 n x 32 columns
        if (tid < 128) {
            int n2 = tid >> 5;          // batch row
            int i  = tid & 31;          // column within slice
            float pr  = sm->gA[i][n2]      + sm->gB[i][n2];
            float pz  = sm->gA[32 + i][n2] + sm->gB[32 + i][n2];
            float ghn = sm->gA[64 + i][n2];
            float gin = sm->gB[64 + i][n2];
            float r = 1.f / (1.f + __expf(-pr));
            float z = 1.f / (1.f + __expf(-pz));
            float npre = fmaf(r, ghn, gin);
            // stable tanh (no inf/inf)
            float tn = 1.f - 2.f / (1.f + __expf(2.f * npre));
            int colg = (bc << 5) + i;
            float hold = sm->Hw[n2][colg];
            float hnew = (1.f - z) * tn + z * hold;
            sm->hbuf[t & 1][n2][i] = hnew;
            int n = gN * 4 + n2;
            g_M[n * M_PER_N + s * 512 + dd * 256 + colg] = hnew;
            if (t == 511)
                g_Mn[n * 512 + dd * 256 + colg] = hnew;
        }

        cluster.sync();

        // pull all 8 slices (incl. own) into local full-h working array
        float* myhb = &sm->hbuf[t & 1][0][0];
        for (int idx = tid; idx < 1024; idx += 384) {
            int src = idx >> 7;
            int rem = idx & 127;
            int n2  = rem >> 5;
            int i2  = rem & 31;
            const float* p = cluster.map_shared_rank(myhb, (unsigned)src);
            sm->Hw[n2][(src << 5) + i2] = p[(n2 << 5) + i2];
        }
        __syncthreads();
    }
}

// ---------------- MLP kernel (1 CTA per n) ----------------
__device__ __forceinline__ void dense_relu(const float* __restrict__ W,
                                           const float* __restrict__ bvec,
                                           const float* __restrict__ in,
                                           float* out, int indim)
{
    int warp = threadIdx.x >> 5, lane = threadIdx.x & 31;
    for (int j = warp * 32; j < warp * 32 + 32; ++j) {
        float acc = 0.f;
        for (int k = lane; k < indim; k += 32)
            acc = fmaf(W[j * indim + k], in[k], acc);
#pragma unroll
        for (int o = 16; o; o >>= 1)
            acc += __shfl_down_sync(0xffffffffu, acc, o);
        if (lane == 0) out[j] = fmaxf(acc + bvec[j], 0.f);
    }
}

__global__ void __launch_bounds__(256)
mlp_kernel(const float* __restrict__ rnn,
           const float* __restrict__ aw0, const float* __restrict__ ab0,
           const float* __restrict__ aw1, const float* __restrict__ ab1,
           const float* __restrict__ alw, const float* __restrict__ alb,
           const float* __restrict__ cw0, const float* __restrict__ cb0,
           const float* __restrict__ cw1, const float* __restrict__ cb1,
           const float* __restrict__ cow, const float* __restrict__ cob)
{
    __shared__ float hn[1024], h1[256], h2[256];
    const int n = blockIdx.x, tid = threadIdx.x;
    const bool newep = (g_nonzero == 0);
    const float* hx = rnn + (size_t)n * TOTAL;
    int P = (int)hx[P_OFF];
    if (P < 0) P = 0; if (P > 511) P = 511;

    // hn = [ Mn interleaved (h*2 + d), r = M[P][n][:] ]
    for (int k = tid; k < 1024; k += 256) {
        float v;
        if (k < 512) {
            int h = k >> 1, d2 = k & 1;
            v = newep ? g_Mn[n * 512 + d2 * 256 + h] : hx[MN_OFF + d2 * 256 + h];
        } else {
            int kk = k - 512;
            v = newep ? g_M[n * M_PER_N + P * 512 + kk] : hx[M_OFF + P * 512 + kk];
        }
        hn[k] = v;
    }
    __syncthreads();

    // actor
    dense_relu(aw0, ab0, hn, h1, 1024);
    __syncthreads();
    dense_relu(aw1, ab1, h1, h2, 256);
    __syncthreads();
    if (tid < 32) {
        float acc = 0.f;
        for (int k = tid; k < 256; k += 32) acc = fmaf(alw[k], h2[k], acc);
#pragma unroll
        for (int o = 16; o; o >>= 1) acc += __shfl_down_sync(0xffffffffu, acc, o);
        if (tid == 0) g_loc[n] = acc + alb[0];
    }
    __syncthreads();

    // critic
    dense_relu(cw0, cb0, hn, h1, 1024);
    __syncthreads();
    dense_relu(cw1, cb1, h1, h2, 256);
    __syncthreads();
    if (tid < 32) {
        float acc = 0.f;
        for (int k = tid; k < 256; k += 32) acc = fmaf(cow[k], h2[k], acc);
#pragma unroll
        for (int o = 16; o; o >>= 1) acc += __shfl_down_sync(0xffffffffu, acc, o);
        if (tid == 0) g_v[n] = acc + cob[0];
    }
}

// ---------------- output fill kernel ----------------
// out is 9 t-slices of (NB, TOTAL): t=0..7 = hx_out, t=8 = hx_out[-1] (== t=7)
__global__ void __launch_bounds__(256)
fill_kernel(const float* __restrict__ inputs, const float* __restrict__ rnn,
            const float* __restrict__ eps, const float* __restrict__ logstd,
            float* __restrict__ out)
{
    int o = blockIdx.x * 256 + threadIdx.x;
    if (o >= TOTAL) return;
    const int t9 = blockIdx.y;
    const int n  = blockIdx.z;
    const int teff = (t9 < 8) ? t9 : 7;
    const float* hx = rnn + (size_t)n * TOTAL;
    const bool newep = (g_nonzero == 0);

    float val;
    if (o >= M_OFF) {
        if (o < MN_OFF) {
            int m = o - M_OFF;
            val = newep ? g_M[n * M_PER_N + m] : hx[o];
        } else {
            val = newep ? g_Mn[n * 512 + (o - MN_OFF)] : hx[o];
        }
    } else if (o >= 4 && o < P_OFF) {
        val = hx[o];                         // hx_h passthrough
    } else if (o == P_OFF) {
        int P = (int)hx[P_OFF];
        val = (float)((P + 1) & 511);        // (P+1) % 512
    } else if (o == 0) {
        float act = inputs[(size_t)(teff * NB + n) * D_IN + (D_IN - 1)];
        float scale = expf(logstd[0]);
        val = (act < 0.f) ? fmaf(scale, eps[teff * NB + n], g_loc[n]) : act;
    } else if (o == 1) {
        val = g_loc[n];
    } else if (o == 2) {
        val = expf(logstd[0]);
    } else { // o == 3
        val = g_v[n];
    }
    out[(size_t)(t9 * NB + n) * TOTAL + o] = val;
}

// ---------------- launch ----------------
extern "C" void kernel_launch(void* const* d_in, const int* in_sizes, int n_in,
                              void* d_out, int out_size)
{
    const float* inputs = (const float*)d_in[0];
    const float* rnn    = (const float*)d_in[1];
    const float* eps    = (const float*)d_in[2];
    const float* gwih   = (const float*)d_in[3];
    const float* gwhh   = (const float*)d_in[4];
    const float* gbih   = (const float*)d_in[5];
    const float* gbhh   = (const float*)d_in[6];
    const float* aw0    = (const float*)d_in[7];
    const float* ab0    = (const float*)d_in[8];
    const float* aw1    = (const float*)d_in[9];
    const float* ab1    = (const float*)d_in[10];
    const float* alw    = (const float*)d_in[11];
    const float* alb    = (const float*)d_in[12];
    const float* alogstd= (const float*)d_in[13];
    const float* cw0    = (const float*)d_in[14];
    const float* cb0    = (const float*)d_in[15];
    const float* cw1    = (const float*)d_in[16];
    const float* cb1    = (const float*)d_in[17];
    const float* cow    = (const float*)d_in[18];
    const float* cob    = (const float*)d_in[19];
    float* out = (float*)d_out;

    (void)in_sizes; (void)n_in; (void)out_size;

    cudaFuncSetAttribute(gru_kernel, cudaFuncAttributeMaxDynamicSharedMemorySize,
                         (int)sizeof(GruSmem));

    reset_flag_kernel<<<1, 1>>>();
    scan_flag_kernel<<<512, 256>>>(rnn);
    gru_kernel<<<dim3(8, 8, 2), 384, sizeof(GruSmem)>>>(inputs, gwih, gwhh, gbih, gbhh);
    mlp_kernel<<<NB, 256>>>(rnn, aw0, ab0, aw1, ab1, alw, alb,
                            cw0, cb0, cw1, cb1, cow, cob);
    fill_kernel<<<dim3((TOTAL + 255) / 256, 9, NB), 256>>>(inputs, rnn, eps, alogstd, out);
}